// round 8
// baseline (speedup 1.0000x reference)
#include <cuda_runtime.h>
#include <cuda_bf16.h>
#include <math.h>
#include <stdint.h>

#define B_  2
#define T_  2048
#define EMB 1024
#define H_  16
#define D_  64
#define M_  (B_ * T_)          // 4096
#define N1  3072
#define N2  1024
#define SCALE 0.125f

// ---------------- scratch (u32 = bf16x2) ----------------
__device__ uint32_t g_xh[4096 * 512], g_xl[4096 * 512];     // x  [m][kpair]
__device__ uint32_t g_wqh[3072 * 512], g_wql[3072 * 512];   // Wqkv^T [n][kpair]
__device__ uint32_t g_woh[1024 * 512], g_wol[1024 * 512];   // Wout^T [n][kpair]
__device__ uint32_t g_Qh[2097152], g_Ql[2097152];           // [bh][t][32 dpair]
__device__ uint32_t g_Kh[2097152], g_Kl[2097152];           // [bh][t][32 dpair]
__device__ uint32_t g_Vh[2097152], g_Vl[2097152];           // [bh][64 d][1024 tpair]
__device__ uint32_t g_Oh[2097152], g_Ol[2097152];           // [m][512 kpair]

// ---------------- helpers ----------------
__device__ __forceinline__ uint32_t pack2(float x, float y) {
    uint32_t r;
    asm("cvt.rn.bf16x2.f32 %0, %1, %2;" : "=r"(r) : "f"(y), "f"(x));  // low=x, high=y
    return r;
}
__device__ __forceinline__ void split2(float x, float y, uint32_t& hi, uint32_t& lo) {
    hi = pack2(x, y);
    __nv_bfloat162 h = *reinterpret_cast<__nv_bfloat162*>(&hi);
    lo = pack2(x - __bfloat162float(h.x), y - __bfloat162float(h.y));
}
__device__ __forceinline__ void mma16(float* c, const uint32_t* a, const uint32_t* b) {
    asm volatile(
        "mma.sync.aligned.m16n8k16.row.col.f32.bf16.bf16.f32 "
        "{%0,%1,%2,%3},{%4,%5,%6,%7},{%8,%9},{%0,%1,%2,%3};\n"
        : "+f"(c[0]), "+f"(c[1]), "+f"(c[2]), "+f"(c[3])
        : "r"(a[0]), "r"(a[1]), "r"(a[2]), "r"(a[3]), "r"(b[0]), "r"(b[1]));
}
__device__ __forceinline__ void ldsm4(uint32_t* r, uint32_t saddr) {
    asm volatile("ldmatrix.sync.aligned.m8n8.x4.shared.b16 {%0,%1,%2,%3}, [%4];"
                 : "=r"(r[0]), "=r"(r[1]), "=r"(r[2]), "=r"(r[3]) : "r"(saddr));
}
__device__ __forceinline__ uint32_t sptr(const void* p) {
    return (uint32_t)__cvta_generic_to_shared(p);
}
__device__ __forceinline__ void cp16(uint32_t saddr, const void* g) {
    asm volatile("cp.async.cg.shared.global [%0], [%1], 16;\n" :: "r"(saddr), "l"(g));
}
#define CP_COMMIT() asm volatile("cp.async.commit_group;\n" ::)
#define CP_WAIT1()  asm volatile("cp.async.wait_group 1;\n" ::)

// ---------------- prep kernels ----------------
__global__ __launch_bounds__(256) void prep_x(const float* __restrict__ x) {
    int i = blockIdx.x * 256 + threadIdx.x;
    float2 v = ((const float2*)x)[i];
    split2(v.x, v.y, g_xh[i], g_xl[i]);
}

// transpose W[1024 k][N n] -> Wt[n][512 kpair], split hi/lo.
template<int N, int SEL>
__global__ __launch_bounds__(256) void prep_w(const float* __restrict__ W) {
    __shared__ uint32_t sh[64][33], sl[64][33];
    const int tid = threadIdx.x;
    const int n0 = blockIdx.x * 64, kp0 = blockIdx.y * 32;
#pragma unroll
    for (int r = 0; r < 8; r++) {
        int kp = r * 4 + (tid >> 6);
        int n  = tid & 63;
        float a = W[(size_t)(2 * (kp0 + kp))     * N + n0 + n];
        float b = W[(size_t)(2 * (kp0 + kp) + 1) * N + n0 + n];
        split2(a, b, sh[n][kp], sl[n][kp]);
    }
    __syncthreads();
    uint32_t* Dh = (SEL == 0) ? g_wqh : g_woh;
    uint32_t* Dl = (SEL == 0) ? g_wql : g_wol;
#pragma unroll
    for (int w = 0; w < 8; w++) {
        int n = w * 8 + (tid >> 5), c = tid & 31;
        Dh[(size_t)(n0 + n) * 512 + kp0 + c] = sh[n][c];
        Dl[(size_t)(n0 + n) * 512 + kp0 + c] = sl[n][c];
    }
}

// ================= GEMM (3xBF16, ldmatrix, cp.async 2-stage) ===============
// Block 128x128, 8 warps (2x4), warp tile 64x32, BK=32 (16 kpairs).
#define GS 20
#define G_ALO 2560
#define G_BHI 5120
#define G_BLO 7680
#define G_STAGE 10240
#define GEMM_SMEM (2 * G_STAGE * 4)

__device__ __forceinline__ void g_load_stage(uint32_t sbase, int kb, int bm, int bn, int tid,
                                             const uint32_t* __restrict__ Ah,
                                             const uint32_t* __restrict__ Al,
                                             const uint32_t* __restrict__ Wh,
                                             const uint32_t* __restrict__ Wl)
{
#pragma unroll
    for (int j = 0; j < 2; j++) {
        int idx = tid + j * 256;
        int row = idx >> 2, c = (idx & 3) * 4;
        size_t srcA = (size_t)(bm + row) * 512 + kb * 16 + c;
        size_t srcB = (size_t)(bn + row) * 512 + kb * 16 + c;
        uint32_t off = (row * GS + c) * 4;
        cp16(sbase + off,               &Ah[srcA]);
        cp16(sbase + G_ALO * 4 + off,   &Al[srcA]);
        cp16(sbase + G_BHI * 4 + off,   &Wh[srcB]);
        cp16(sbase + G_BLO * 4 + off,   &Wl[srcB]);
    }
}

template<int MODE>
__global__ __launch_bounds__(256, 2) void gemmb(const float* __restrict__ bias,
                                                float* __restrict__ C)
{
    extern __shared__ uint32_t smem_g[];
    const uint32_t* Ah = (MODE == 0) ? g_xh  : g_Oh;
    const uint32_t* Al = (MODE == 0) ? g_xl  : g_Ol;
    const uint32_t* Wh = (MODE == 0) ? g_wqh : g_woh;
    const uint32_t* Wl = (MODE == 0) ? g_wql : g_wol;

    const int tid  = threadIdx.x;
    const int warp = tid >> 5, lane = tid & 31;
    const int g    = lane >> 2, tg = lane & 3;
    const int wy   = warp >> 2, wx = warp & 3;
    const int bm   = blockIdx.y * 128, bn = blockIdx.x * 128;

    float acc[4][4][4];
#pragma unroll
    for (int i = 0; i < 4; i++)
#pragma unroll
        for (int j = 0; j < 4; j++)
#pragma unroll
            for (int r = 0; r < 4; r++) acc[i][j][r] = 0.f;

    const uint32_t sbase = sptr(smem_g);
    const int a_row = wy * 64 + (lane & 15);
    const int a_col = (lane >> 4) * 4;
    const int b_row = wx * 32 + ((lane >> 4) & 1) * 8 + (lane & 7);
    const int b_col = ((lane >> 3) & 1) * 4;

    g_load_stage(sbase, 0, bm, bn, tid, Ah, Al, Wh, Wl);
    CP_COMMIT();
    g_load_stage(sbase + G_STAGE * 4, 1, bm, bn, tid, Ah, Al, Wh, Wl);
    CP_COMMIT();

    for (int kb = 0; kb < 32; kb++) {
        CP_WAIT1();
        __syncthreads();
        const uint32_t st = sbase + (kb & 1) * (G_STAGE * 4);

#pragma unroll
        for (int ka = 0; ka < 2; ka++) {
            uint32_t ah[4][4], al[4][4], bb[2][4];
            // B hi + A hi
#pragma unroll
            for (int nb = 0; nb < 2; nb++)
                ldsm4(bb[nb], st + G_BHI * 4 + ((b_row + nb * 16) * GS + ka * 8 + b_col) * 4);
#pragma unroll
            for (int ma = 0; ma < 4; ma++)
                ldsm4(ah[ma], st + ((a_row + ma * 16) * GS + ka * 8 + a_col) * 4);
            // pass hh: 16 independent accs
#pragma unroll
            for (int ma = 0; ma < 4; ma++)
#pragma unroll
                for (int na = 0; na < 4; na++)
                    mma16(acc[ma][na], ah[ma], &bb[na >> 1][(na & 1) * 2]);
            // A lo, pass lh
#pragma unroll
            for (int ma = 0; ma < 4; ma++)
                ldsm4(al[ma], st + G_ALO * 4 + ((a_row + ma * 16) * GS + ka * 8 + a_col) * 4);
#pragma unroll
            for (int ma = 0; ma < 4; ma++)
#pragma unroll
                for (int na = 0; na < 4; na++)
                    mma16(acc[ma][na], al[ma], &bb[na >> 1][(na & 1) * 2]);
            // B lo (overwrite bb), pass hl
#pragma unroll
            for (int nb = 0; nb < 2; nb++)
                ldsm4(bb[nb], st + G_BLO * 4 + ((b_row + nb * 16) * GS + ka * 8 + b_col) * 4);
#pragma unroll
            for (int ma = 0; ma < 4; ma++)
#pragma unroll
                for (int na = 0; na < 4; na++)
                    mma16(acc[ma][na], ah[ma], &bb[na >> 1][(na & 1) * 2]);
        }
        __syncthreads();
        if (kb + 2 < 32)
            g_load_stage(st, kb + 2, bm, bn, tid, Ah, Al, Wh, Wl);
        CP_COMMIT();
    }

    // ---------- epilogue ----------
#pragma unroll
    for (int ma = 0; ma < 4; ma++) {
        int m0 = bm + wy * 64 + ma * 16 + g;
#pragma unroll
        for (int na = 0; na < 4; na++) {
            int n = bn + wx * 32 + na * 8 + tg * 2;
            float b0v = bias[n], b1v = bias[n + 1];
#pragma unroll
            for (int half = 0; half < 2; half++) {
                int m = m0 + half * 8;
                float vx = acc[ma][na][half * 2 + 0] + b0v;
                float vy = acc[ma][na][half * 2 + 1] + b1v;
                if (MODE == 0) {
                    int bb2 = m >> 11, t = m & (T_ - 1);
                    int sec = n >> 10, rem = n & 1023;
                    int h = rem >> 6, d = rem & 63;
                    int bhh = bb2 * H_ + h;
                    if (sec == 0) {
                        vx *= SCALE; vy *= SCALE;
                        uint32_t hi, lo;
                        split2(vx, vy, hi, lo);
                        size_t idx = ((size_t)bhh * T_ + t) * 32 + (d >> 1);
                        g_Qh[idx] = hi; g_Ql[idx] = lo;
                    } else if (sec == 1) {
                        uint32_t hi, lo;
                        split2(vx, vy, hi, lo);
                        size_t idx = ((size_t)bhh * T_ + t) * 32 + (d >> 1);
                        g_Kh[idx] = hi; g_Kl[idx] = lo;
                    } else {
                        __nv_bfloat16 hx = __float2bfloat16(vx);
                        __nv_bfloat16 hy = __float2bfloat16(vy);
                        __nv_bfloat16 lx = __float2bfloat16(vx - __bfloat162float(hx));
                        __nv_bfloat16 ly = __float2bfloat16(vy - __bfloat162float(hy));
                        size_t ix = (((size_t)bhh * 64 + d) * 1024 + (t >> 1)) * 2 + (t & 1);
                        __nv_bfloat16* Vh = reinterpret_cast<__nv_bfloat16*>(g_Vh);
                        __nv_bfloat16* Vl = reinterpret_cast<__nv_bfloat16*>(g_Vl);
                        Vh[ix] = hx; Vh[ix + 2048] = hy;
                        Vl[ix] = lx; Vl[ix + 2048] = ly;
                    }
                } else {
                    float2 v; v.x = vx; v.y = vy;
                    *(float2*)&C[(size_t)m * N2 + n] = v;
                }
            }
        }
    }
}

// ================= Attention (3xBF16 flash, ldmatrix, 2-stage) =============
#define ATS 36
#define A_KLO 2304
#define A_VHI 4608
#define A_VLO 6912
#define A_STAGE 9216
#define ATTN_SMEM (2 * A_STAGE * 4)

__device__ __forceinline__ void a_load_stage(uint32_t sbase, int bh, int base, int tid)
{
#pragma unroll
    for (int j = 0; j < 2; j++) {
        int i = tid + j * 256;
        int r = i >> 3, c = (i & 7) * 4;
        uint32_t off = (r * ATS + c) * 4;
        size_t srcK = ((size_t)bh * T_ + base + r) * 32 + c;
        size_t srcV = ((size_t)bh * 64 + r) * 1024 + (base >> 1) + c;
        cp16(sbase + off,               &g_Kh[srcK]);
        cp16(sbase + A_KLO * 4 + off,   &g_Kl[srcK]);
        cp16(sbase + A_VHI * 4 + off,   &g_Vh[srcV]);
        cp16(sbase + A_VLO * 4 + off,   &g_Vl[srcV]);
    }
}

__global__ __launch_bounds__(256, 2) void attnb()
{
    extern __shared__ uint32_t sm[];
    const int tid = threadIdx.x, warp = tid >> 5, lane = tid & 31;
    const int g = lane >> 2, tg = lane & 3;
    const int qb = gridDim.x - 1 - blockIdx.x;     // heavy tiles first
    const int bh = blockIdx.y;
    const int wrow = warp * 16;
    const int qr0  = qb * 128 + wrow;

    const uint32_t sbase = sptr(sm);
    const int f_row = ((lane >> 4) & 1) * 8 + (lane & 7);
    const int f_col = ((lane >> 3) & 1) * 4;

    uint32_t qfh[4][4], qfl[4][4];
    {
        size_t r0 = ((size_t)bh * T_ + qr0 + g) * 32;
        size_t r8 = r0 + 8 * 32;
#pragma unroll
        for (int ka = 0; ka < 4; ka++) {
            int kp = ka * 8 + tg;
            qfh[ka][0] = g_Qh[r0 + kp];     qfl[ka][0] = g_Ql[r0 + kp];
            qfh[ka][1] = g_Qh[r8 + kp];     qfl[ka][1] = g_Ql[r8 + kp];
            qfh[ka][2] = g_Qh[r0 + kp + 4]; qfl[ka][2] = g_Ql[r0 + kp + 4];
            qfh[ka][3] = g_Qh[r8 + kp + 4]; qfl[ka][3] = g_Ql[r8 + kp + 4];
        }
    }

    float of[8][4];
#pragma unroll
    for (int j = 0; j < 8; j++)
#pragma unroll
        for (int r = 0; r < 4; r++) of[j][r] = 0.f;

    const float NEG_INF = __int_as_float(0xff800000);
    float mrow[2] = {NEG_INF, NEG_INF};
    float lrow[2] = {0.f, 0.f};

    const int ntiles = 2 * qb + 2;
    a_load_stage(sbase, bh, 0, tid);
    CP_COMMIT();

    for (int kt = 0; kt < ntiles; kt++) {
        const int base = kt * 64;
        __syncthreads();
        if (kt + 1 < ntiles)
            a_load_stage(sbase + ((kt + 1) & 1) * (A_STAGE * 4), bh, base + 64, tid);
        CP_COMMIT();
        CP_WAIT1();
        __syncthreads();

        if (base > qr0 + 15) continue;
        const uint32_t st = sbase + (kt & 1) * (A_STAGE * 4);

        // ---- S = Q K^T (3 passes per ka: hh, lh over K-hi; then hl over K-lo) ----
        float sacc[8][4];
#pragma unroll
        for (int j = 0; j < 8; j++)
#pragma unroll
            for (int r = 0; r < 4; r++) sacc[j][r] = 0.f;

#pragma unroll
        for (int ka = 0; ka < 4; ka++) {
            uint32_t kk[4][4];
#pragma unroll
            for (int nb = 0; nb < 4; nb++)
                ldsm4(kk[nb], st + ((f_row + nb * 16) * ATS + ka * 8 + f_col) * 4);
#pragma unroll
            for (int nb = 0; nb < 4; nb++) {
                mma16(sacc[2 * nb],     qfh[ka], &kk[nb][0]);
                mma16(sacc[2 * nb + 1], qfh[ka], &kk[nb][2]);
            }
#pragma unroll
            for (int nb = 0; nb < 4; nb++) {
                mma16(sacc[2 * nb],     qfl[ka], &kk[nb][0]);
                mma16(sacc[2 * nb + 1], qfl[ka], &kk[nb][2]);
            }
#pragma unroll
            for (int nb = 0; nb < 4; nb++)
                ldsm4(kk[nb], st + A_KLO * 4 + ((f_row + nb * 16) * ATS + ka * 8 + f_col) * 4);
#pragma unroll
            for (int nb = 0; nb < 4; nb++) {
                mma16(sacc[2 * nb],     qfh[ka], &kk[nb][0]);
                mma16(sacc[2 * nb + 1], qfh[ka], &kk[nb][2]);
            }
        }

        // ---- causal mask ----
        if (base + 63 > qr0) {
#pragma unroll
            for (int na = 0; na < 8; na++)
#pragma unroll
                for (int r = 0; r < 4; r++) {
                    int q = qr0 + g + (r >> 1) * 8;
                    int j = base + na * 8 + tg * 2 + (r & 1);
                    if (j > q) sacc[na][r] = NEG_INF;
                }
        }

        // ---- online softmax ----
#pragma unroll
        for (int h = 0; h < 2; h++) {
            float rm = NEG_INF;
#pragma unroll
            for (int na = 0; na < 8; na++) {
                rm = fmaxf(rm, sacc[na][h * 2 + 0]);
                rm = fmaxf(rm, sacc[na][h * 2 + 1]);
            }
            rm = fmaxf(rm, __shfl_xor_sync(0xffffffffu, rm, 1));
            rm = fmaxf(rm, __shfl_xor_sync(0xffffffffu, rm, 2));
            float mn   = fmaxf(mrow[h], rm);
            float corr = __expf(mrow[h] - mn);
            mrow[h] = mn;
            float sum = 0.f;
#pragma unroll
            for (int na = 0; na < 8; na++) {
                float p0 = __expf(sacc[na][h * 2 + 0] - mn);
                float p1 = __expf(sacc[na][h * 2 + 1] - mn);
                sacc[na][h * 2 + 0] = p0;
                sacc[na][h * 2 + 1] = p1;
                sum += p0 + p1;
            }
            sum += __shfl_xor_sync(0xffffffffu, sum, 1);
            sum += __shfl_xor_sync(0xffffffffu, sum, 2);
            lrow[h] = lrow[h] * corr + sum;
#pragma unroll
            for (int na = 0; na < 8; na++) {
                of[na][h * 2 + 0] *= corr;
                of[na][h * 2 + 1] *= corr;
            }
        }

        // ---- O += P V (register P; 3 passes over V hi/lo) ----
#pragma unroll
        for (int ka = 0; ka < 4; ka++) {
            uint32_t pah[4], pal[4];
            split2(sacc[2 * ka][0],     sacc[2 * ka][1],     pah[0], pal[0]);
            split2(sacc[2 * ka][2],     sacc[2 * ka][3],     pah[1], pal[1]);
            split2(sacc[2 * ka + 1][0], sacc[2 * ka + 1][1], pah[2], pal[2]);
            split2(sacc[2 * ka + 1][2], sacc[2 * ka + 1][3], pah[3], pal[3]);
            uint32_t vv[4][4];
#pragma unroll
            for (int nb = 0; nb < 4; nb++)
                ldsm4(vv[nb], st + A_VHI * 4 + ((f_row + nb * 16) * ATS + ka * 8 + f_col) * 4);
#pragma unroll
            for (int nb = 0; nb < 4; nb++) {
                mma16(of[2 * nb],     pah, &vv[nb][0]);
                mma16(of[2 * nb + 1], pah, &vv[nb][2]);
            }
#pragma unroll
            for (int nb = 0; nb < 4; nb++) {
                mma16(of[2 * nb],     pal, &vv[nb][0]);
                mma16(of[2 * nb + 1], pal, &vv[nb][2]);
            }
#pragma unroll
            for (int nb = 0; nb < 4; nb++)
                ldsm4(vv[nb], st + A_VLO * 4 + ((f_row + nb * 16) * ATS + ka * 8 + f_col) * 4);
#pragma unroll
            for (int nb = 0; nb < 4; nb++) {
                mma16(of[2 * nb],     pah, &vv[nb][0]);
                mma16(of[2 * nb + 1], pah, &vv[nb][2]);
            }
        }
    }

    // ---- finalize ----
    const int bb = bh >> 4, hh = bh & 15;
    float inv0 = 1.f / lrow[0];
    float inv1 = 1.f / lrow[1];
    int q = qb * 128 + wrow + g;
    size_t r0 = (size_t)(bb * T_ + q) * 512 + hh * 32;
    size_t r8 = r0 + 8 * 512;
#pragma unroll
    for (int na = 0; na < 8; na++) {
        int dp = (na * 8 + tg * 2) >> 1;
        uint32_t h0, l0, h1, l1;
        split2(of[na][0] * inv0, of[na][1] * inv0, h0, l0);
        split2(of[na][2] * inv1, of[na][3] * inv1, h1, l1);
        g_Oh[r0 + dp] = h0;  g_Ol[r0 + dp] = l0;
        g_Oh[r8 + dp] = h1;  g_Ol[r8 + dp] = l1;
    }
}

// ---------------- launch ----------------
extern "C" void kernel_launch(void* const* d_in, const int* in_sizes, int n_in,
                              void* d_out, int out_size)
{
    const float* x    = (const float*)d_in[0];
    const float* Wqkv = (const float*)d_in[1];
    const float* bqkv = (const float*)d_in[2];
    const float* Wout = (const float*)d_in[3];
    const float* bout = (const float*)d_in[4];
    float* out = (float*)d_out;

    static bool attr_done = false;
    if (!attr_done) {
        cudaFuncSetAttribute((void*)gemmb<0>, cudaFuncAttributeMaxDynamicSharedMemorySize, GEMM_SMEM);
        cudaFuncSetAttribute((void*)gemmb<1>, cudaFuncAttributeMaxDynamicSharedMemorySize, GEMM_SMEM);
        cudaFuncSetAttribute((void*)attnb,    cudaFuncAttributeMaxDynamicSharedMemorySize, ATTN_SMEM);
        attr_done = true;
    }

    prep_x<<<4096 * 512 / 256, 256>>>(x);
    prep_w<N1, 0><<<dim3(N1 / 64, 16), 256>>>(Wqkv);
    prep_w<N2, 1><<<dim3(N2 / 64, 16), 256>>>(Wout);

    dim3 g1(N1 / 128, M_ / 128);   // (24, 32)
    gemmb<0><<<g1, 256, GEMM_SMEM>>>(bqkv, nullptr);

    dim3 ga(T_ / 128, B_ * H_);    // (16, 32)
    attnb<<<ga, 256, ATTN_SMEM>>>();

    dim3 g2(N2 / 128, M_ / 128);   // (8, 32)
    gemmb<1><<<g2, 256, GEMM_SMEM>>>(bout, out);
}

// round 9
// speedup vs baseline: 1.1476x; 1.1476x over previous
#include <cuda_runtime.h>
#include <cuda_fp16.h>
#include <math.h>
#include <stdint.h>

#define B_  2
#define T_  2048
#define EMB 1024
#define H_  16
#define D_  64
#define M_  (B_ * T_)          // 4096
#define N1  3072
#define N2  1024
#define SCALE 0.125f

// ---------------- scratch (u32 = fp16x2) ----------------
__device__ uint32_t g_xh[4096 * 512], g_xl[4096 * 512];     // x  [m][kpair]
__device__ uint32_t g_wqh[3072 * 512], g_wql[3072 * 512];   // Wqkv^T [n][kpair]
__device__ uint32_t g_woh[1024 * 512];                      // Wout^T [n][kpair] hi only
__device__ uint32_t g_Qh[2097152], g_Ql[2097152];           // [bh][t][32 dpair]
__device__ uint32_t g_Kh[2097152], g_Kl[2097152];           // [bh][t][32 dpair]
__device__ uint32_t g_Vh[2097152];                          // [bh][64 d][1024 tpair] hi only
__device__ uint32_t g_Oh[2097152], g_Ol[2097152];           // [m][512 kpair]

// ---------------- helpers ----------------
__device__ __forceinline__ uint32_t pack2(float x, float y) {   // low=x, high=y
    uint32_t r;
    asm("cvt.rn.f16x2.f32 %0, %1, %2;" : "=r"(r) : "f"(y), "f"(x));
    return r;
}
__device__ __forceinline__ void split2(float x, float y, uint32_t& hi, uint32_t& lo) {
    hi = pack2(x, y);
    __half2 h = *reinterpret_cast<__half2*>(&hi);
    lo = pack2(x - __half2float(h.x), y - __half2float(h.y));
}
__device__ __forceinline__ void mma16(float* c, const uint32_t* a, const uint32_t* b) {
    asm volatile(
        "mma.sync.aligned.m16n8k16.row.col.f32.f16.f16.f32 "
        "{%0,%1,%2,%3},{%4,%5,%6,%7},{%8,%9},{%0,%1,%2,%3};\n"
        : "+f"(c[0]), "+f"(c[1]), "+f"(c[2]), "+f"(c[3])
        : "r"(a[0]), "r"(a[1]), "r"(a[2]), "r"(a[3]), "r"(b[0]), "r"(b[1]));
}
__device__ __forceinline__ void ldsm4(uint32_t* r, uint32_t saddr) {
    asm volatile("ldmatrix.sync.aligned.m8n8.x4.shared.b16 {%0,%1,%2,%3}, [%4];"
                 : "=r"(r[0]), "=r"(r[1]), "=r"(r[2]), "=r"(r[3]) : "r"(saddr));
}
__device__ __forceinline__ uint32_t sptr(const void* p) {
    return (uint32_t)__cvta_generic_to_shared(p);
}
__device__ __forceinline__ void cp16(uint32_t saddr, const void* g) {
    asm volatile("cp.async.cg.shared.global [%0], [%1], 16;\n" :: "r"(saddr), "l"(g));
}
#define CP_COMMIT() asm volatile("cp.async.commit_group;\n" ::)
#define CP_WAIT1()  asm volatile("cp.async.wait_group 1;\n" ::)

// ---------------- prep kernels ----------------
__global__ __launch_bounds__(256) void prep_x(const float* __restrict__ x) {
    int i = blockIdx.x * 256 + threadIdx.x;
    float2 v = ((const float2*)x)[i];
    split2(v.x, v.y, g_xh[i], g_xl[i]);
}

// transpose W[1024 k][N n] -> Wt[n][512 kpair], split hi/lo (SEL1: hi only).
template<int N, int SEL>
__global__ __launch_bounds__(256) void prep_w(const float* __restrict__ W) {
    __shared__ uint32_t sh[64][33], sl[64][33];
    const int tid = threadIdx.x;
    const int n0 = blockIdx.x * 64, kp0 = blockIdx.y * 32;
#pragma unroll
    for (int r = 0; r < 8; r++) {
        int kp = r * 4 + (tid >> 6);
        int n  = tid & 63;
        float a = W[(size_t)(2 * (kp0 + kp))     * N + n0 + n];
        float b = W[(size_t)(2 * (kp0 + kp) + 1) * N + n0 + n];
        split2(a, b, sh[n][kp], sl[n][kp]);
    }
    __syncthreads();
#pragma unroll
    for (int w = 0; w < 8; w++) {
        int n = w * 8 + (tid >> 5), c = tid & 31;
        if (SEL == 0) {
            g_wqh[(size_t)(n0 + n) * 512 + kp0 + c] = sh[n][c];
            g_wql[(size_t)(n0 + n) * 512 + kp0 + c] = sl[n][c];
        } else {
            g_woh[(size_t)(n0 + n) * 512 + kp0 + c] = sh[n][c];
        }
    }
}

// ================= GEMM (ldmatrix, cp.async 2-stage) =======================
// Block 128x128, 8 warps (2x4), warp tile 64x32, BK=32 (16 kpairs).
// MODE 0 (QKV): 3-pass (hh, lh, hl).  MODE 1 (out): 2-pass (hh, lh), no B-lo.
#define GS 20
#define G_ALO 2560
#define G_BHI 5120
#define G_BLO 7680
#define G_STAGE 10240
#define GEMM_SMEM (2 * G_STAGE * 4)

template<int MODE>
__device__ __forceinline__ void g_load_stage(uint32_t sbase, int kb, int bm, int bn, int tid,
                                             const uint32_t* __restrict__ Ah,
                                             const uint32_t* __restrict__ Al,
                                             const uint32_t* __restrict__ Wh,
                                             const uint32_t* __restrict__ Wl)
{
#pragma unroll
    for (int j = 0; j < 2; j++) {
        int idx = tid + j * 256;
        int row = idx >> 2, c = (idx & 3) * 4;
        size_t srcA = (size_t)(bm + row) * 512 + kb * 16 + c;
        size_t srcB = (size_t)(bn + row) * 512 + kb * 16 + c;
        uint32_t off = (row * GS + c) * 4;
        cp16(sbase + off,               &Ah[srcA]);
        cp16(sbase + G_ALO * 4 + off,   &Al[srcA]);
        cp16(sbase + G_BHI * 4 + off,   &Wh[srcB]);
        if (MODE == 0) cp16(sbase + G_BLO * 4 + off, &Wl[srcB]);
    }
}

template<int MODE>
__global__ __launch_bounds__(256, 2) void gemmb(const float* __restrict__ bias,
                                                float* __restrict__ C)
{
    extern __shared__ uint32_t smem_g[];
    const uint32_t* Ah = (MODE == 0) ? g_xh  : g_Oh;
    const uint32_t* Al = (MODE == 0) ? g_xl  : g_Ol;
    const uint32_t* Wh = (MODE == 0) ? g_wqh : g_woh;
    const uint32_t* Wl = (MODE == 0) ? g_wql : g_woh;   // unused in MODE 1

    const int tid  = threadIdx.x;
    const int warp = tid >> 5, lane = tid & 31;
    const int g    = lane >> 2, tg = lane & 3;
    const int wy   = warp >> 2, wx = warp & 3;
    const int bm   = blockIdx.y * 128, bn = blockIdx.x * 128;

    float acc[4][4][4];
#pragma unroll
    for (int i = 0; i < 4; i++)
#pragma unroll
        for (int j = 0; j < 4; j++)
#pragma unroll
            for (int r = 0; r < 4; r++) acc[i][j][r] = 0.f;

    const uint32_t sbase = sptr(smem_g);
    const int a_row = wy * 64 + (lane & 15);
    const int a_col = (lane >> 4) * 4;
    const int b_row = wx * 32 + ((lane >> 4) & 1) * 8 + (lane & 7);
    const int b_col = ((lane >> 3) & 1) * 4;

    g_load_stage<MODE>(sbase, 0, bm, bn, tid, Ah, Al, Wh, Wl);
    CP_COMMIT();
    g_load_stage<MODE>(sbase + G_STAGE * 4, 1, bm, bn, tid, Ah, Al, Wh, Wl);
    CP_COMMIT();

    for (int kb = 0; kb < 32; kb++) {
        CP_WAIT1();
        __syncthreads();
        const uint32_t st = sbase + (kb & 1) * (G_STAGE * 4);

#pragma unroll
        for (int ka = 0; ka < 2; ka++) {
            uint32_t kbh[2][4], kbl[2][4];
#pragma unroll
            for (int nb = 0; nb < 2; nb++) {
                uint32_t off = ((b_row + nb * 16) * GS + ka * 8 + b_col) * 4;
                ldsm4(kbh[nb], st + G_BHI * 4 + off);
                if (MODE == 0) ldsm4(kbl[nb], st + G_BLO * 4 + off);
            }
#pragma unroll
            for (int ma = 0; ma < 4; ma++) {
                uint32_t off = ((a_row + ma * 16) * GS + ka * 8 + a_col) * 4;
                uint32_t ah[4], al[4];
                ldsm4(ah, st + off);
                ldsm4(al, st + G_ALO * 4 + off);
#pragma unroll
                for (int na = 0; na < 4; na++) {
                    const uint32_t* b2h = &kbh[na >> 1][(na & 1) * 2];
                    mma16(acc[ma][na], ah, b2h);
                    mma16(acc[ma][na], al, b2h);
                    if (MODE == 0) {
                        const uint32_t* b2l = &kbl[na >> 1][(na & 1) * 2];
                        mma16(acc[ma][na], ah, b2l);
                    }
                }
            }
        }
        __syncthreads();
        if (kb + 2 < 32)
            g_load_stage<MODE>(st, kb + 2, bm, bn, tid, Ah, Al, Wh, Wl);
        CP_COMMIT();
    }

    // ---------- epilogue ----------
#pragma unroll
    for (int ma = 0; ma < 4; ma++) {
        int m0 = bm + wy * 64 + ma * 16 + g;
#pragma unroll
        for (int na = 0; na < 4; na++) {
            int n = bn + wx * 32 + na * 8 + tg * 2;
            float b0v = bias[n], b1v = bias[n + 1];
#pragma unroll
            for (int half = 0; half < 2; half++) {
                int m = m0 + half * 8;
                float vx = acc[ma][na][half * 2 + 0] + b0v;
                float vy = acc[ma][na][half * 2 + 1] + b1v;
                if (MODE == 0) {
                    int bb2 = m >> 11, t = m & (T_ - 1);
                    int sec = n >> 10, rem = n & 1023;
                    int h = rem >> 6, d = rem & 63;
                    int bhh = bb2 * H_ + h;
                    if (sec == 0) {
                        vx *= SCALE; vy *= SCALE;
                        uint32_t hi, lo;
                        split2(vx, vy, hi, lo);
                        size_t idx = ((size_t)bhh * T_ + t) * 32 + (d >> 1);
                        g_Qh[idx] = hi; g_Ql[idx] = lo;
                    } else if (sec == 1) {
                        uint32_t hi, lo;
                        split2(vx, vy, hi, lo);
                        size_t idx = ((size_t)bhh * T_ + t) * 32 + (d >> 1);
                        g_Kh[idx] = hi; g_Kl[idx] = lo;
                    } else {
                        __half hx = __float2half_rn(vx);
                        __half hy = __float2half_rn(vy);
                        size_t ix = (((size_t)bhh * 64 + d) * 1024 + (t >> 1)) * 2 + (t & 1);
                        __half* Vh = reinterpret_cast<__half*>(g_Vh);
                        Vh[ix] = hx; Vh[ix + 2048] = hy;   // d+1 -> +1024 u32 = +2048 halfs
                    }
                } else {
                    float2 v; v.x = vx; v.y = vy;
                    *(float2*)&C[(size_t)m * N2 + n] = v;
                }
            }
        }
    }
}

// ================= Attention (fp16 flash, ldmatrix, 2-stage) ===============
// Stage: K_hi[64 t][ATS], K_lo, V_hi[64 d][ATS]  (cols = 32 pairs + pad)
#define ATS 36
#define A_KLO 2304
#define A_VHI 4608
#define A_STAGE 6912
#define ATTN_SMEM (2 * A_STAGE * 4)

__device__ __forceinline__ void a_load_stage(uint32_t sbase, int bh, int base, int tid)
{
#pragma unroll
    for (int j = 0; j < 2; j++) {
        int i = tid + j * 256;
        int r = i >> 3, c = (i & 7) * 4;
        uint32_t off = (r * ATS + c) * 4;
        size_t srcK = ((size_t)bh * T_ + base + r) * 32 + c;
        size_t srcV = ((size_t)bh * 64 + r) * 1024 + (base >> 1) + c;
        cp16(sbase + off,               &g_Kh[srcK]);
        cp16(sbase + A_KLO * 4 + off,   &g_Kl[srcK]);
        cp16(sbase + A_VHI * 4 + off,   &g_Vh[srcV]);
    }
}

__global__ __launch_bounds__(256, 2) void attnb()
{
    extern __shared__ uint32_t sm[];
    const int tid = threadIdx.x, warp = tid >> 5, lane = tid & 31;
    const int g = lane >> 2, tg = lane & 3;
    const int qb = blockIdx.x, bh = blockIdx.y;
    const int wrow = warp * 16;
    const int qr0  = qb * 128 + wrow;

    const uint32_t sbase = sptr(sm);
    const int f_row = ((lane >> 4) & 1) * 8 + (lane & 7);
    const int f_col = ((lane >> 3) & 1) * 4;

    uint32_t qfh[4][4], qfl[4][4];
    {
        size_t r0 = ((size_t)bh * T_ + qr0 + g) * 32;
        size_t r8 = r0 + 8 * 32;
#pragma unroll
        for (int ka = 0; ka < 4; ka++) {
            int kp = ka * 8 + tg;
            qfh[ka][0] = g_Qh[r0 + kp];     qfl[ka][0] = g_Ql[r0 + kp];
            qfh[ka][1] = g_Qh[r8 + kp];     qfl[ka][1] = g_Ql[r8 + kp];
            qfh[ka][2] = g_Qh[r0 + kp + 4]; qfl[ka][2] = g_Ql[r0 + kp + 4];
            qfh[ka][3] = g_Qh[r8 + kp + 4]; qfl[ka][3] = g_Ql[r8 + kp + 4];
        }
    }

    float of[8][4];
#pragma unroll
    for (int j = 0; j < 8; j++)
#pragma unroll
        for (int r = 0; r < 4; r++) of[j][r] = 0.f;

    const float NEG_INF = __int_as_float(0xff800000);
    float mrow[2] = {NEG_INF, NEG_INF};
    float lrow[2] = {0.f, 0.f};

    const int ntiles = 2 * qb + 2;
    a_load_stage(sbase, bh, 0, tid);
    CP_COMMIT();

    for (int kt = 0; kt < ntiles; kt++) {
        const int base = kt * 64;
        __syncthreads();
        if (kt + 1 < ntiles)
            a_load_stage(sbase + ((kt + 1) & 1) * (A_STAGE * 4), bh, base + 64, tid);
        CP_COMMIT();
        CP_WAIT1();
        __syncthreads();

        if (base > qr0 + 15) continue;
        const uint32_t st = sbase + (kt & 1) * (A_STAGE * 4);

        // ---- S = Q K^T (3-pass fp16) ----
        float sacc[8][4];
#pragma unroll
        for (int j = 0; j < 8; j++)
#pragma unroll
            for (int r = 0; r < 4; r++) sacc[j][r] = 0.f;

#pragma unroll
        for (int nb = 0; nb < 4; nb++) {
#pragma unroll
            for (int ka = 0; ka < 4; ka++) {
                uint32_t off = ((f_row + nb * 16) * ATS + ka * 8 + f_col) * 4;
                uint32_t kh4[4], kl4[4];
                ldsm4(kh4, st + off);
                ldsm4(kl4, st + A_KLO * 4 + off);
                mma16(sacc[2 * nb],     qfh[ka], &kh4[0]);
                mma16(sacc[2 * nb],     qfl[ka], &kh4[0]);
                mma16(sacc[2 * nb],     qfh[ka], &kl4[0]);
                mma16(sacc[2 * nb + 1], qfh[ka], &kh4[2]);
                mma16(sacc[2 * nb + 1], qfl[ka], &kh4[2]);
                mma16(sacc[2 * nb + 1], qfh[ka], &kl4[2]);
            }
        }

        // ---- causal mask ----
        if (base + 63 > qr0) {
#pragma unroll
            for (int na = 0; na < 8; na++)
#pragma unroll
                for (int r = 0; r < 4; r++) {
                    int q = qr0 + g + (r >> 1) * 8;
                    int j = base + na * 8 + tg * 2 + (r & 1);
                    if (j > q) sacc[na][r] = NEG_INF;
                }
        }

        // ---- online softmax ----
#pragma unroll
        for (int h = 0; h < 2; h++) {
            float rm = NEG_INF;
#pragma unroll
            for (int na = 0; na < 8; na++) {
                rm = fmaxf(rm, sacc[na][h * 2 + 0]);
                rm = fmaxf(rm, sacc[na][h * 2 + 1]);
            }
            rm = fmaxf(rm, __shfl_xor_sync(0xffffffffu, rm, 1));
            rm = fmaxf(rm, __shfl_xor_sync(0xffffffffu, rm, 2));
            float mn   = fmaxf(mrow[h], rm);
            float corr = __expf(mrow[h] - mn);
            mrow[h] = mn;
            float sum = 0.f;
#pragma unroll
            for (int na = 0; na < 8; na++) {
                float p0 = __expf(sacc[na][h * 2 + 0] - mn);
                float p1 = __expf(sacc[na][h * 2 + 1] - mn);
                sacc[na][h * 2 + 0] = p0;
                sacc[na][h * 2 + 1] = p1;
                sum += p0 + p1;
            }
            sum += __shfl_xor_sync(0xffffffffu, sum, 1);
            sum += __shfl_xor_sync(0xffffffffu, sum, 2);
            lrow[h] = lrow[h] * corr + sum;
#pragma unroll
            for (int na = 0; na < 8; na++) {
                of[na][h * 2 + 0] *= corr;
                of[na][h * 2 + 1] *= corr;
            }
        }

        // ---- O += P V (register P 2-term, V hi-only: 2-pass) ----
#pragma unroll
        for (int ka = 0; ka < 4; ka++) {
            uint32_t pah[4], pal[4];
            split2(sacc[2 * ka][0],     sacc[2 * ka][1],     pah[0], pal[0]);
            split2(sacc[2 * ka][2],     sacc[2 * ka][3],     pah[1], pal[1]);
            split2(sacc[2 * ka + 1][0], sacc[2 * ka + 1][1], pah[2], pal[2]);
            split2(sacc[2 * ka + 1][2], sacc[2 * ka + 1][3], pah[3], pal[3]);
#pragma unroll
            for (int nb = 0; nb < 4; nb++) {
                uint32_t off = ((f_row + nb * 16) * ATS + ka * 8 + f_col) * 4;
                uint32_t vh4[4];
                ldsm4(vh4, st + A_VHI * 4 + off);
                mma16(of[2 * nb],     pah, &vh4[0]);
                mma16(of[2 * nb],     pal, &vh4[0]);
                mma16(of[2 * nb + 1], pah, &vh4[2]);
                mma16(of[2 * nb + 1], pal, &vh4[2]);
            }
        }
    }

    // ---- finalize: write O hi/lo fp16 pairs ----
    const int bb = bh >> 4, hh = bh & 15;
    float inv0 = 1.f / lrow[0];
    float inv1 = 1.f / lrow[1];
    int q = qb * 128 + wrow + g;
    size_t r0 = (size_t)(bb * T_ + q) * 512 + hh * 32;
    size_t r8 = r0 + 8 * 512;
#pragma unroll
    for (int na = 0; na < 8; na++) {
        int dp = (na * 8 + tg * 2) >> 1;
        uint32_t h0, l0, h1, l1;
        split2(of[na][0] * inv0, of[na][1] * inv0, h0, l0);
        split2(of[na][2] * inv1, of[na][3] * inv1, h1, l1);
        g_Oh[r0 + dp] = h0;  g_Ol[r0 + dp] = l0;
        g_Oh[r8 + dp] = h1;  g_Ol[r8 + dp] = l1;
    }
}

// ---------------- launch ----------------
extern "C" void kernel_launch(void* const* d_in, const int* in_sizes, int n_in,
                              void* d_out, int out_size)
{
    const float* x    = (const float*)d_in[0];
    const float* Wqkv = (const float*)d_in[1];
    const float* bqkv = (const float*)d_in[2];
    const float* Wout = (const float*)d_in[3];
    const float* bout = (const float*)d_in[4];
    float* out = (float*)d_out;

    static bool attr_done = false;
    if (!attr_done) {
        cudaFuncSetAttribute((void*)gemmb<0>, cudaFuncAttributeMaxDynamicSharedMemorySize, GEMM_SMEM);
        cudaFuncSetAttribute((void*)gemmb<1>, cudaFuncAttributeMaxDynamicSharedMemorySize, GEMM_SMEM);
        cudaFuncSetAttribute((void*)attnb,    cudaFuncAttributeMaxDynamicSharedMemorySize, ATTN_SMEM);
        attr_done = true;
    }

    prep_x<<<4096 * 512 / 256, 256>>>(x);
    prep_w<N1, 0><<<dim3(N1 / 64, 16), 256>>>(Wqkv);
    prep_w<N2, 1><<<dim3(N2 / 64, 16), 256>>>(Wout);

    dim3 g1(N1 / 128, M_ / 128);   // (24, 32)
    gemmb<0><<<g1, 256, GEMM_SMEM>>>(bqkv, nullptr);

    dim3 ga(T_ / 128, B_ * H_);    // (16, 32)
    attnb<<<ga, 256, ATTN_SMEM>>>();

    dim3 g2(N2 / 128, M_ / 128);   // (8, 32)
    gemmb<1><<<g2, 256, GEMM_SMEM>>>(bout, out);
}

// round 10
// speedup vs baseline: 1.4708x; 1.2817x over previous
#include <cuda_runtime.h>
#include <cuda_fp16.h>
#include <math.h>
#include <stdint.h>

#define B_  2
#define T_  2048
#define EMB 1024
#define H_  16
#define D_  64
#define M_  (B_ * T_)          // 4096
#define N1  3072
#define N2  1024
#define SCALE 0.125f

// ---------------- scratch (u32 = fp16x2) ----------------
__device__ uint32_t g_xh[4096 * 512], g_xl[4096 * 512];     // x  [m][kpair] 2-term
__device__ uint32_t g_wqh[3072 * 512];                      // Wqkv^T [n][kpair] hi only
__device__ uint32_t g_woh[1024 * 512];                      // Wout^T [n][kpair] hi only
__device__ uint32_t g_Qh[2097152], g_Ql[2097152];           // [bh][t][32 dpair] 2-term
__device__ uint32_t g_Kh[2097152];                          // [bh][t][32 dpair] hi only
__device__ uint32_t g_Vh[2097152];                          // [bh][64 d][1024 tpair] hi only
__device__ uint32_t g_Oh[2097152], g_Ol[2097152];           // [m][512 kpair] 2-term

// ---------------- helpers ----------------
__device__ __forceinline__ uint32_t pack2(float x, float y) {   // low=x, high=y
    uint32_t r;
    asm("cvt.rn.f16x2.f32 %0, %1, %2;" : "=r"(r) : "f"(y), "f"(x));
    return r;
}
__device__ __forceinline__ void split2(float x, float y, uint32_t& hi, uint32_t& lo) {
    hi = pack2(x, y);
    __half2 h = *reinterpret_cast<__half2*>(&hi);
    lo = pack2(x - __half2float(h.x), y - __half2float(h.y));
}
__device__ __forceinline__ void mma16(float* c, const uint32_t* a, const uint32_t* b) {
    asm volatile(
        "mma.sync.aligned.m16n8k16.row.col.f32.f16.f16.f32 "
        "{%0,%1,%2,%3},{%4,%5,%6,%7},{%8,%9},{%0,%1,%2,%3};\n"
        : "+f"(c[0]), "+f"(c[1]), "+f"(c[2]), "+f"(c[3])
        : "r"(a[0]), "r"(a[1]), "r"(a[2]), "r"(a[3]), "r"(b[0]), "r"(b[1]));
}
__device__ __forceinline__ void ldsm4(uint32_t* r, uint32_t saddr) {
    asm volatile("ldmatrix.sync.aligned.m8n8.x4.shared.b16 {%0,%1,%2,%3}, [%4];"
                 : "=r"(r[0]), "=r"(r[1]), "=r"(r[2]), "=r"(r[3]) : "r"(saddr));
}
__device__ __forceinline__ uint32_t sptr(const void* p) {
    return (uint32_t)__cvta_generic_to_shared(p);
}
__device__ __forceinline__ void cp16(uint32_t saddr, const void* g) {
    asm volatile("cp.async.cg.shared.global [%0], [%1], 16;\n" :: "r"(saddr), "l"(g));
}
#define CP_COMMIT() asm volatile("cp.async.commit_group;\n" ::)
#define CP_WAIT1()  asm volatile("cp.async.wait_group 1;\n" ::)

// ---------------- prep kernels ----------------
__global__ __launch_bounds__(256) void prep_x(const float* __restrict__ x) {
    int i = blockIdx.x * 256 + threadIdx.x;
    float2 v = ((const float2*)x)[i];
    split2(v.x, v.y, g_xh[i], g_xl[i]);
}

// transpose W[1024 k][N n] -> Wt[n][512 kpair], hi only.
template<int N, int SEL>
__global__ __launch_bounds__(256) void prep_w(const float* __restrict__ W) {
    __shared__ uint32_t sh[64][33];
    const int tid = threadIdx.x;
    const int n0 = blockIdx.x * 64, kp0 = blockIdx.y * 32;
#pragma unroll
    for (int r = 0; r < 8; r++) {
        int kp = r * 4 + (tid >> 6);
        int n  = tid & 63;
        float a = W[(size_t)(2 * (kp0 + kp))     * N + n0 + n];
        float b = W[(size_t)(2 * (kp0 + kp) + 1) * N + n0 + n];
        sh[n][kp] = pack2(a, b);
    }
    __syncthreads();
    uint32_t* Dh = (SEL == 0) ? g_wqh : g_woh;
#pragma unroll
    for (int w = 0; w < 8; w++) {
        int n = w * 8 + (tid >> 5), c = tid & 31;
        Dh[(size_t)(n0 + n) * 512 + kp0 + c] = sh[n][c];
    }
}

// ================= GEMM (2-pass: (Ah+Al)*Wh, ldmatrix, cp.async 2-stage) ===
// Block 128x128, 8 warps (2x4), warp tile 64x32, BK=32 (16 kpairs).
#define GS 20
#define G_ALO 2560
#define G_BHI 5120
#define G_STAGE 7680
#define GEMM_SMEM (2 * G_STAGE * 4)

__device__ __forceinline__ void g_load_stage(uint32_t sbase, int kb, int bm, int bn, int tid,
                                             const uint32_t* __restrict__ Ah,
                                             const uint32_t* __restrict__ Al,
                                             const uint32_t* __restrict__ Wh)
{
#pragma unroll
    for (int j = 0; j < 2; j++) {
        int idx = tid + j * 256;
        int row = idx >> 2, c = (idx & 3) * 4;
        size_t srcA = (size_t)(bm + row) * 512 + kb * 16 + c;
        size_t srcB = (size_t)(bn + row) * 512 + kb * 16 + c;
        uint32_t off = (row * GS + c) * 4;
        cp16(sbase + off,               &Ah[srcA]);
        cp16(sbase + G_ALO * 4 + off,   &Al[srcA]);
        cp16(sbase + G_BHI * 4 + off,   &Wh[srcB]);
    }
}

template<int MODE>
__global__ __launch_bounds__(256, 2) void gemmb(const float* __restrict__ bias,
                                                float* __restrict__ C)
{
    extern __shared__ uint32_t smem_g[];
    const uint32_t* Ah = (MODE == 0) ? g_xh  : g_Oh;
    const uint32_t* Al = (MODE == 0) ? g_xl  : g_Ol;
    const uint32_t* Wh = (MODE == 0) ? g_wqh : g_woh;

    const int tid  = threadIdx.x;
    const int warp = tid >> 5, lane = tid & 31;
    const int g    = lane >> 2, tg = lane & 3;
    const int wy   = warp >> 2, wx = warp & 3;
    const int bm   = blockIdx.y * 128, bn = blockIdx.x * 128;

    float acc[4][4][4];
#pragma unroll
    for (int i = 0; i < 4; i++)
#pragma unroll
        for (int j = 0; j < 4; j++)
#pragma unroll
            for (int r = 0; r < 4; r++) acc[i][j][r] = 0.f;

    const uint32_t sbase = sptr(smem_g);
    const int a_row = wy * 64 + (lane & 15);
    const int a_col = (lane >> 4) * 4;
    const int b_row = wx * 32 + ((lane >> 4) & 1) * 8 + (lane & 7);
    const int b_col = ((lane >> 3) & 1) * 4;

    g_load_stage(sbase, 0, bm, bn, tid, Ah, Al, Wh);
    CP_COMMIT();
    g_load_stage(sbase + G_STAGE * 4, 1, bm, bn, tid, Ah, Al, Wh);
    CP_COMMIT();

    for (int kb = 0; kb < 32; kb++) {
        CP_WAIT1();
        __syncthreads();
        const uint32_t st = sbase + (kb & 1) * (G_STAGE * 4);

#pragma unroll
        for (int ka = 0; ka < 2; ka++) {
            uint32_t kbh[2][4];
#pragma unroll
            for (int nb = 0; nb < 2; nb++) {
                uint32_t off = ((b_row + nb * 16) * GS + ka * 8 + b_col) * 4;
                ldsm4(kbh[nb], st + G_BHI * 4 + off);
            }
#pragma unroll
            for (int ma = 0; ma < 4; ma++) {
                uint32_t off = ((a_row + ma * 16) * GS + ka * 8 + a_col) * 4;
                uint32_t ah[4], al[4];
                ldsm4(ah, st + off);
                ldsm4(al, st + G_ALO * 4 + off);
#pragma unroll
                for (int na = 0; na < 4; na++) {
                    const uint32_t* b2h = &kbh[na >> 1][(na & 1) * 2];
                    mma16(acc[ma][na], ah, b2h);
                    mma16(acc[ma][na], al, b2h);
                }
            }
        }
        __syncthreads();
        if (kb + 2 < 32)
            g_load_stage(st, kb + 2, bm, bn, tid, Ah, Al, Wh);
        CP_COMMIT();
    }

    // ---------- epilogue ----------
#pragma unroll
    for (int ma = 0; ma < 4; ma++) {
        int m0 = bm + wy * 64 + ma * 16 + g;
#pragma unroll
        for (int na = 0; na < 4; na++) {
            int n = bn + wx * 32 + na * 8 + tg * 2;
            float b0v = bias[n], b1v = bias[n + 1];
#pragma unroll
            for (int half = 0; half < 2; half++) {
                int m = m0 + half * 8;
                float vx = acc[ma][na][half * 2 + 0] + b0v;
                float vy = acc[ma][na][half * 2 + 1] + b1v;
                if (MODE == 0) {
                    int bb2 = m >> 11, t = m & (T_ - 1);
                    int sec = n >> 10, rem = n & 1023;
                    int h = rem >> 6, d = rem & 63;
                    int bhh = bb2 * H_ + h;
                    if (sec == 0) {
                        vx *= SCALE; vy *= SCALE;
                        uint32_t hi, lo;
                        split2(vx, vy, hi, lo);
                        size_t idx = ((size_t)bhh * T_ + t) * 32 + (d >> 1);
                        g_Qh[idx] = hi; g_Ql[idx] = lo;
                    } else if (sec == 1) {
                        size_t idx = ((size_t)bhh * T_ + t) * 32 + (d >> 1);
                        g_Kh[idx] = pack2(vx, vy);
                    } else {
                        __half hx = __float2half_rn(vx);
                        __half hy = __float2half_rn(vy);
                        size_t ix = (((size_t)bhh * 64 + d) * 1024 + (t >> 1)) * 2 + (t & 1);
                        __half* Vh = reinterpret_cast<__half*>(g_Vh);
                        Vh[ix] = hx; Vh[ix + 2048] = hy;   // d+1 -> +1024 u32 = +2048 halfs
                    }
                } else {
                    float2 v; v.x = vx; v.y = vy;
                    *(float2*)&C[(size_t)m * N2 + n] = v;
                }
            }
        }
    }
}

// ================= Attention (fp16 flash, K hi-only, ldmatrix, 2-stage) ====
// Stage: K_hi[64 t][ATS], V_hi[64 d][ATS]  (cols = 32 pairs + pad)
#define ATS 36
#define A_VHI 2304
#define A_STAGE 4608
#define ATTN_SMEM (2 * A_STAGE * 4)

__device__ __forceinline__ void a_load_stage(uint32_t sbase, int bh, int base, int tid)
{
#pragma unroll
    for (int j = 0; j < 2; j++) {
        int i = tid + j * 256;
        int r = i >> 3, c = (i & 7) * 4;
        uint32_t off = (r * ATS + c) * 4;
        size_t srcK = ((size_t)bh * T_ + base + r) * 32 + c;
        size_t srcV = ((size_t)bh * 64 + r) * 1024 + (base >> 1) + c;
        cp16(sbase + off,               &g_Kh[srcK]);
        cp16(sbase + A_VHI * 4 + off,   &g_Vh[srcV]);
    }
}

__global__ __launch_bounds__(256, 2) void attnb()
{
    extern __shared__ uint32_t sm[];
    const int tid = threadIdx.x, warp = tid >> 5, lane = tid & 31;
    const int g = lane >> 2, tg = lane & 3;
    const int qb = blockIdx.x, bh = blockIdx.y;
    const int wrow = warp * 16;
    const int qr0  = qb * 128 + wrow;

    const uint32_t sbase = sptr(sm);
    const int f_row = ((lane >> 4) & 1) * 8 + (lane & 7);
    const int f_col = ((lane >> 3) & 1) * 4;

    uint32_t qfh[4][4], qfl[4][4];
    {
        size_t r0 = ((size_t)bh * T_ + qr0 + g) * 32;
        size_t r8 = r0 + 8 * 32;
#pragma unroll
        for (int ka = 0; ka < 4; ka++) {
            int kp = ka * 8 + tg;
            qfh[ka][0] = g_Qh[r0 + kp];     qfl[ka][0] = g_Ql[r0 + kp];
            qfh[ka][1] = g_Qh[r8 + kp];     qfl[ka][1] = g_Ql[r8 + kp];
            qfh[ka][2] = g_Qh[r0 + kp + 4]; qfl[ka][2] = g_Ql[r0 + kp + 4];
            qfh[ka][3] = g_Qh[r8 + kp + 4]; qfl[ka][3] = g_Ql[r8 + kp + 4];
        }
    }

    float of[8][4];
#pragma unroll
    for (int j = 0; j < 8; j++)
#pragma unroll
        for (int r = 0; r < 4; r++) of[j][r] = 0.f;

    const float NEG_INF = __int_as_float(0xff800000);
    float mrow[2] = {NEG_INF, NEG_INF};
    float lrow[2] = {0.f, 0.f};

    const int ntiles = 2 * qb + 2;
    a_load_stage(sbase, bh, 0, tid);
    CP_COMMIT();

    for (int kt = 0; kt < ntiles; kt++) {
        const int base = kt * 64;
        __syncthreads();
        if (kt + 1 < ntiles)
            a_load_stage(sbase + ((kt + 1) & 1) * (A_STAGE * 4), bh, base + 64, tid);
        CP_COMMIT();
        CP_WAIT1();
        __syncthreads();

        if (base > qr0 + 15) continue;
        const uint32_t st = sbase + (kt & 1) * (A_STAGE * 4);

        // ---- S = (Qh+Ql) Kh^T (2-pass) ----
        float sacc[8][4];
#pragma unroll
        for (int j = 0; j < 8; j++)
#pragma unroll
            for (int r = 0; r < 4; r++) sacc[j][r] = 0.f;

#pragma unroll
        for (int nb = 0; nb < 4; nb++) {
#pragma unroll
            for (int ka = 0; ka < 4; ka++) {
                uint32_t off = ((f_row + nb * 16) * ATS + ka * 8 + f_col) * 4;
                uint32_t kh4[4];
                ldsm4(kh4, st + off);
                mma16(sacc[2 * nb],     qfh[ka], &kh4[0]);
                mma16(sacc[2 * nb],     qfl[ka], &kh4[0]);
                mma16(sacc[2 * nb + 1], qfh[ka], &kh4[2]);
                mma16(sacc[2 * nb + 1], qfl[ka], &kh4[2]);
            }
        }

        // ---- causal mask ----
        if (base + 63 > qr0) {
#pragma unroll
            for (int na = 0; na < 8; na++)
#pragma unroll
                for (int r = 0; r < 4; r++) {
                    int q = qr0 + g + (r >> 1) * 8;
                    int j = base + na * 8 + tg * 2 + (r & 1);
                    if (j > q) sacc[na][r] = NEG_INF;
                }
        }

        // ---- online softmax ----
#pragma unroll
        for (int h = 0; h < 2; h++) {
            float rm = NEG_INF;
#pragma unroll
            for (int na = 0; na < 8; na++) {
                rm = fmaxf(rm, sacc[na][h * 2 + 0]);
                rm = fmaxf(rm, sacc[na][h * 2 + 1]);
            }
            rm = fmaxf(rm, __shfl_xor_sync(0xffffffffu, rm, 1));
            rm = fmaxf(rm, __shfl_xor_sync(0xffffffffu, rm, 2));
            float mn   = fmaxf(mrow[h], rm);
            float corr = __expf(mrow[h] - mn);
            mrow[h] = mn;
            float sum = 0.f;
#pragma unroll
            for (int na = 0; na < 8; na++) {
                float p0 = __expf(sacc[na][h * 2 + 0] - mn);
                float p1 = __expf(sacc[na][h * 2 + 1] - mn);
                sacc[na][h * 2 + 0] = p0;
                sacc[na][h * 2 + 1] = p1;
                sum += p0 + p1;
            }
            sum += __shfl_xor_sync(0xffffffffu, sum, 1);
            sum += __shfl_xor_sync(0xffffffffu, sum, 2);
            lrow[h] = lrow[h] * corr + sum;
#pragma unroll
            for (int na = 0; na < 8; na++) {
                of[na][h * 2 + 0] *= corr;
                of[na][h * 2 + 1] *= corr;
            }
        }

        // ---- O += P V (register P 2-term, V hi-only) ----
#pragma unroll
        for (int ka = 0; ka < 4; ka++) {
            uint32_t pah[4], pal[4];
            split2(sacc[2 * ka][0],     sacc[2 * ka][1],     pah[0], pal[0]);
            split2(sacc[2 * ka][2],     sacc[2 * ka][3],     pah[1], pal[1]);
            split2(sacc[2 * ka + 1][0], sacc[2 * ka + 1][1], pah[2], pal[2]);
            split2(sacc[2 * ka + 1][2], sacc[2 * ka + 1][3], pah[3], pal[3]);
#pragma unroll
            for (int nb = 0; nb < 4; nb++) {
                uint32_t off = ((f_row + nb * 16) * ATS + ka * 8 + f_col) * 4;
                uint32_t vh4[4];
                ldsm4(vh4, st + A_VHI * 4 + off);
                mma16(of[2 * nb],     pah, &vh4[0]);
                mma16(of[2 * nb],     pal, &vh4[0]);
                mma16(of[2 * nb + 1], pah, &vh4[2]);
                mma16(of[2 * nb + 1], pal, &vh4[2]);
            }
        }
    }

    // ---- finalize: write O hi/lo fp16 pairs ----
    const int bb = bh >> 4, hh = bh & 15;
    float inv0 = 1.f / lrow[0];
    float inv1 = 1.f / lrow[1];
    int q = qb * 128 + wrow + g;
    size_t r0 = (size_t)(bb * T_ + q) * 512 + hh * 32;
    size_t r8 = r0 + 8 * 512;
#pragma unroll
    for (int na = 0; na < 8; na++) {
        int dp = (na * 8 + tg * 2) >> 1;
        uint32_t h0, l0, h1, l1;
        split2(of[na][0] * inv0, of[na][1] * inv0, h0, l0);
        split2(of[na][2] * inv1, of[na][3] * inv1, h1, l1);
        g_Oh[r0 + dp] = h0;  g_Ol[r0 + dp] = l0;
        g_Oh[r8 + dp] = h1;  g_Ol[r8 + dp] = l1;
    }
}

// ---------------- launch ----------------
extern "C" void kernel_launch(void* const* d_in, const int* in_sizes, int n_in,
                              void* d_out, int out_size)
{
    const float* x    = (const float*)d_in[0];
    const float* Wqkv = (const float*)d_in[1];
    const float* bqkv = (const float*)d_in[2];
    const float* Wout = (const float*)d_in[3];
    const float* bout = (const float*)d_in[4];
    float* out = (float*)d_out;

    static bool attr_done = false;
    if (!attr_done) {
        cudaFuncSetAttribute((void*)gemmb<0>, cudaFuncAttributeMaxDynamicSharedMemorySize, GEMM_SMEM);
        cudaFuncSetAttribute((void*)gemmb<1>, cudaFuncAttributeMaxDynamicSharedMemorySize, GEMM_SMEM);
        cudaFuncSetAttribute((void*)attnb,    cudaFuncAttributeMaxDynamicSharedMemorySize, ATTN_SMEM);
        attr_done = true;
    }

    prep_x<<<4096 * 512 / 256, 256>>>(x);
    prep_w<N1, 0><<<dim3(N1 / 64, 16), 256>>>(Wqkv);
    prep_w<N2, 1><<<dim3(N2 / 64, 16), 256>>>(Wout);

    dim3 g1(N1 / 128, M_ / 128);   // (24, 32)
    gemmb<0><<<g1, 256, GEMM_SMEM>>>(bqkv, nullptr);

    dim3 ga(T_ / 128, B_ * H_);    // (16, 32)
    attnb<<<ga, 256, ATTN_SMEM>>>();

    dim3 g2(N2 / 128, M_ / 128);   // (8, 32)
    gemmb<1><<<g2, 256, GEMM_SMEM>>>(bout, out);
}

// round 11
// speedup vs baseline: 2.3436x; 1.5934x over previous
#include <cuda_runtime.h>
#include <cuda_fp16.h>
#include <math.h>
#include <stdint.h>

#define B_  2
#define T_  2048
#define EMB 1024
#define H_  16
#define D_  64
#define M_  (B_ * T_)          // 4096
#define N1  3072
#define N2  1024
#define SCALE 0.125f

// ---------------- scratch (u32 = fp16x2, hi-only everywhere) ----------------
__device__ uint32_t g_xh[4096 * 512];        // x  [m][kpair]
__device__ uint32_t g_wqh[3072 * 512];       // Wqkv^T [n][kpair]
__device__ uint32_t g_woh[1024 * 512];       // Wout^T [n][kpair]
__device__ uint32_t g_Qh[2097152];           // [bh][t][32 dpair]
__device__ uint32_t g_Kh[2097152];           // [bh][t][32 dpair]
__device__ uint32_t g_Vh[2097152];           // [bh][64 d][1024 tpair]
__device__ uint32_t g_Oh[2097152];           // [m][512 kpair]

// ---------------- helpers ----------------
__device__ __forceinline__ uint32_t pack2(float x, float y) {   // low=x, high=y
    uint32_t r;
    asm("cvt.rn.f16x2.f32 %0, %1, %2;" : "=r"(r) : "f"(y), "f"(x));
    return r;
}
__device__ __forceinline__ void mma16(float* c, const uint32_t* a, const uint32_t* b) {
    asm volatile(
        "mma.sync.aligned.m16n8k16.row.col.f32.f16.f16.f32 "
        "{%0,%1,%2,%3},{%4,%5,%6,%7},{%8,%9},{%0,%1,%2,%3};\n"
        : "+f"(c[0]), "+f"(c[1]), "+f"(c[2]), "+f"(c[3])
        : "r"(a[0]), "r"(a[1]), "r"(a[2]), "r"(a[3]), "r"(b[0]), "r"(b[1]));
}
__device__ __forceinline__ void ldsm4(uint32_t* r, uint32_t saddr) {
    asm volatile("ldmatrix.sync.aligned.m8n8.x4.shared.b16 {%0,%1,%2,%3}, [%4];"
                 : "=r"(r[0]), "=r"(r[1]), "=r"(r[2]), "=r"(r[3]) : "r"(saddr));
}
__device__ __forceinline__ uint32_t sptr(const void* p) {
    return (uint32_t)__cvta_generic_to_shared(p);
}
__device__ __forceinline__ void cp16(uint32_t saddr, const void* g) {
    asm volatile("cp.async.cg.shared.global [%0], [%1], 16;\n" :: "r"(saddr), "l"(g));
}
#define CP_COMMIT() asm volatile("cp.async.commit_group;\n" ::)
#define CP_WAIT1()  asm volatile("cp.async.wait_group 1;\n" ::)

// ---------------- prep kernels ----------------
__global__ __launch_bounds__(256) void prep_x(const float* __restrict__ x) {
    int i = blockIdx.x * 256 + threadIdx.x;
    float2 v = ((const float2*)x)[i];
    g_xh[i] = pack2(v.x, v.y);
}

// transpose W[1024 k][N n] -> Wt[n][512 kpair], hi only.
template<int N, int SEL>
__global__ __launch_bounds__(256) void prep_w(const float* __restrict__ W) {
    __shared__ uint32_t sh[64][33];
    const int tid = threadIdx.x;
    const int n0 = blockIdx.x * 64, kp0 = blockIdx.y * 32;
#pragma unroll
    for (int r = 0; r < 8; r++) {
        int kp = r * 4 + (tid >> 6);
        int n  = tid & 63;
        float a = W[(size_t)(2 * (kp0 + kp))     * N + n0 + n];
        float b = W[(size_t)(2 * (kp0 + kp) + 1) * N + n0 + n];
        sh[n][kp] = pack2(a, b);
    }
    __syncthreads();
    uint32_t* Dh = (SEL == 0) ? g_wqh : g_woh;
#pragma unroll
    for (int w = 0; w < 8; w++) {
        int n = w * 8 + (tid >> 5), c = tid & 31;
        Dh[(size_t)(n0 + n) * 512 + kp0 + c] = sh[n][c];
    }
}

// ================= GEMM (1-pass fp16, ldmatrix, cp.async 2-stage) ==========
// Block 128x128, 8 warps (2x4), warp tile 64x32, BK=32 (16 kpairs).
#define GS 20
#define G_BHI 2560
#define G_STAGE 5120
#define GEMM_SMEM (2 * G_STAGE * 4)

__device__ __forceinline__ void g_load_stage(uint32_t sbase, int kb, int bm, int bn, int tid,
                                             const uint32_t* __restrict__ Ah,
                                             const uint32_t* __restrict__ Wh)
{
#pragma unroll
    for (int j = 0; j < 2; j++) {
        int idx = tid + j * 256;
        int row = idx >> 2, c = (idx & 3) * 4;
        size_t srcA = (size_t)(bm + row) * 512 + kb * 16 + c;
        size_t srcB = (size_t)(bn + row) * 512 + kb * 16 + c;
        uint32_t off = (row * GS + c) * 4;
        cp16(sbase + off,             &Ah[srcA]);
        cp16(sbase + G_BHI * 4 + off, &Wh[srcB]);
    }
}

template<int MODE>
__global__ __launch_bounds__(256, 2) void gemmb(const float* __restrict__ bias,
                                                float* __restrict__ C)
{
    extern __shared__ uint32_t smem_g[];
    const uint32_t* Ah = (MODE == 0) ? g_xh  : g_Oh;
    const uint32_t* Wh = (MODE == 0) ? g_wqh : g_woh;

    const int tid  = threadIdx.x;
    const int warp = tid >> 5, lane = tid & 31;
    const int g    = lane >> 2, tg = lane & 3;
    const int wy   = warp >> 2, wx = warp & 3;
    const int bm   = blockIdx.y * 128, bn = blockIdx.x * 128;

    float acc[4][4][4];
#pragma unroll
    for (int i = 0; i < 4; i++)
#pragma unroll
        for (int j = 0; j < 4; j++)
#pragma unroll
            for (int r = 0; r < 4; r++) acc[i][j][r] = 0.f;

    const uint32_t sbase = sptr(smem_g);
    const int a_row = wy * 64 + (lane & 15);
    const int a_col = (lane >> 4) * 4;
    const int b_row = wx * 32 + ((lane >> 4) & 1) * 8 + (lane & 7);
    const int b_col = ((lane >> 3) & 1) * 4;

    g_load_stage(sbase, 0, bm, bn, tid, Ah, Wh);
    CP_COMMIT();
    g_load_stage(sbase + G_STAGE * 4, 1, bm, bn, tid, Ah, Wh);
    CP_COMMIT();

    for (int kb = 0; kb < 32; kb++) {
        CP_WAIT1();
        __syncthreads();
        const uint32_t st = sbase + (kb & 1) * (G_STAGE * 4);

#pragma unroll
        for (int ka = 0; ka < 2; ka++) {
            uint32_t kbh[2][4];
#pragma unroll
            for (int nb = 0; nb < 2; nb++) {
                uint32_t off = ((b_row + nb * 16) * GS + ka * 8 + b_col) * 4;
                ldsm4(kbh[nb], st + G_BHI * 4 + off);
            }
#pragma unroll
            for (int ma = 0; ma < 4; ma++) {
                uint32_t off = ((a_row + ma * 16) * GS + ka * 8 + a_col) * 4;
                uint32_t ah[4];
                ldsm4(ah, st + off);
#pragma unroll
                for (int na = 0; na < 4; na++)
                    mma16(acc[ma][na], ah, &kbh[na >> 1][(na & 1) * 2]);
            }
        }
        __syncthreads();
        if (kb + 2 < 32)
            g_load_stage(st, kb + 2, bm, bn, tid, Ah, Wh);
        CP_COMMIT();
    }

    // ---------- epilogue ----------
#pragma unroll
    for (int ma = 0; ma < 4; ma++) {
        int m0 = bm + wy * 64 + ma * 16 + g;
#pragma unroll
        for (int na = 0; na < 4; na++) {
            int n = bn + wx * 32 + na * 8 + tg * 2;
            float b0v = bias[n], b1v = bias[n + 1];
#pragma unroll
            for (int half = 0; half < 2; half++) {
                int m = m0 + half * 8;
                float vx = acc[ma][na][half * 2 + 0] + b0v;
                float vy = acc[ma][na][half * 2 + 1] + b1v;
                if (MODE == 0) {
                    int bb2 = m >> 11, t = m & (T_ - 1);
                    int sec = n >> 10, rem = n & 1023;
                    int h = rem >> 6, d = rem & 63;
                    int bhh = bb2 * H_ + h;
                    if (sec == 0) {
                        size_t idx = ((size_t)bhh * T_ + t) * 32 + (d >> 1);
                        g_Qh[idx] = pack2(vx * SCALE, vy * SCALE);
                    } else if (sec == 1) {
                        size_t idx = ((size_t)bhh * T_ + t) * 32 + (d >> 1);
                        g_Kh[idx] = pack2(vx, vy);
                    } else {
                        __half hx = __float2half_rn(vx);
                        __half hy = __float2half_rn(vy);
                        size_t ix = (((size_t)bhh * 64 + d) * 1024 + (t >> 1)) * 2 + (t & 1);
                        __half* Vh = reinterpret_cast<__half*>(g_Vh);
                        Vh[ix] = hx; Vh[ix + 2048] = hy;   // d+1 -> +1024 u32 = +2048 halfs
                    }
                } else {
                    float2 v; v.x = vx; v.y = vy;
                    *(float2*)&C[(size_t)m * N2 + n] = v;
                }
            }
        }
    }
}

// ================= Attention (1-pass fp16 flash, ldmatrix, 2-stage) ========
// Stage: K_hi[64 t][ATS], V_hi[64 d][ATS]  (cols = 32 pairs + pad)
#define ATS 36
#define A_VHI 2304
#define A_STAGE 4608
#define ATTN_SMEM (2 * A_STAGE * 4)

__device__ __forceinline__ void a_load_stage(uint32_t sbase, int bh, int base, int tid)
{
#pragma unroll
    for (int j = 0; j < 2; j++) {
        int i = tid + j * 256;
        int r = i >> 3, c = (i & 7) * 4;
        uint32_t off = (r * ATS + c) * 4;
        size_t srcK = ((size_t)bh * T_ + base + r) * 32 + c;
        size_t srcV = ((size_t)bh * 64 + r) * 1024 + (base >> 1) + c;
        cp16(sbase + off,             &g_Kh[srcK]);
        cp16(sbase + A_VHI * 4 + off, &g_Vh[srcV]);
    }
}

__global__ __launch_bounds__(256, 2) void attnb()
{
    extern __shared__ uint32_t sm[];
    const int tid = threadIdx.x, warp = tid >> 5, lane = tid & 31;
    const int g = lane >> 2, tg = lane & 3;
    const int qb = blockIdx.x, bh = blockIdx.y;
    const int wrow = warp * 16;
    const int qr0  = qb * 128 + wrow;

    const uint32_t sbase = sptr(sm);
    const int f_row = ((lane >> 4) & 1) * 8 + (lane & 7);
    const int f_col = ((lane >> 3) & 1) * 4;

    uint32_t qfh[4][4];
    {
        size_t r0 = ((size_t)bh * T_ + qr0 + g) * 32;
        size_t r8 = r0 + 8 * 32;
#pragma unroll
        for (int ka = 0; ka < 4; ka++) {
            int kp = ka * 8 + tg;
            qfh[ka][0] = g_Qh[r0 + kp];
            qfh[ka][1] = g_Qh[r8 + kp];
            qfh[ka][2] = g_Qh[r0 + kp + 4];
            qfh[ka][3] = g_Qh[r8 + kp + 4];
        }
    }

    float of[8][4];
#pragma unroll
    for (int j = 0; j < 8; j++)
#pragma unroll
        for (int r = 0; r < 4; r++) of[j][r] = 0.f;

    const float NEG_INF = __int_as_float(0xff800000);
    float mrow[2] = {NEG_INF, NEG_INF};
    float lrow[2] = {0.f, 0.f};

    const int ntiles = 2 * qb + 2;
    a_load_stage(sbase, bh, 0, tid);
    CP_COMMIT();

    for (int kt = 0; kt < ntiles; kt++) {
        const int base = kt * 64;
        __syncthreads();
        if (kt + 1 < ntiles)
            a_load_stage(sbase + ((kt + 1) & 1) * (A_STAGE * 4), bh, base + 64, tid);
        CP_COMMIT();
        CP_WAIT1();
        __syncthreads();

        if (base > qr0 + 15) continue;
        const uint32_t st = sbase + (kt & 1) * (A_STAGE * 4);

        // ---- S = Q K^T (1-pass) ----
        float sacc[8][4];
#pragma unroll
        for (int j = 0; j < 8; j++)
#pragma unroll
            for (int r = 0; r < 4; r++) sacc[j][r] = 0.f;

#pragma unroll
        for (int nb = 0; nb < 4; nb++) {
#pragma unroll
            for (int ka = 0; ka < 4; ka++) {
                uint32_t off = ((f_row + nb * 16) * ATS + ka * 8 + f_col) * 4;
                uint32_t kh4[4];
                ldsm4(kh4, st + off);
                mma16(sacc[2 * nb],     qfh[ka], &kh4[0]);
                mma16(sacc[2 * nb + 1], qfh[ka], &kh4[2]);
            }
        }

        // ---- causal mask ----
        if (base + 63 > qr0) {
#pragma unroll
            for (int na = 0; na < 8; na++)
#pragma unroll
                for (int r = 0; r < 4; r++) {
                    int q = qr0 + g + (r >> 1) * 8;
                    int j = base + na * 8 + tg * 2 + (r & 1);
                    if (j > q) sacc[na][r] = NEG_INF;
                }
        }

        // ---- online softmax ----
#pragma unroll
        for (int h = 0; h < 2; h++) {
            float rm = NEG_INF;
#pragma unroll
            for (int na = 0; na < 8; na++) {
                rm = fmaxf(rm, sacc[na][h * 2 + 0]);
                rm = fmaxf(rm, sacc[na][h * 2 + 1]);
            }
            rm = fmaxf(rm, __shfl_xor_sync(0xffffffffu, rm, 1));
            rm = fmaxf(rm, __shfl_xor_sync(0xffffffffu, rm, 2));
            float mn   = fmaxf(mrow[h], rm);
            float corr = __expf(mrow[h] - mn);
            mrow[h] = mn;
            float sum = 0.f;
#pragma unroll
            for (int na = 0; na < 8; na++) {
                float p0 = __expf(sacc[na][h * 2 + 0] - mn);
                float p1 = __expf(sacc[na][h * 2 + 1] - mn);
                sacc[na][h * 2 + 0] = p0;
                sacc[na][h * 2 + 1] = p1;
                sum += p0 + p1;
            }
            sum += __shfl_xor_sync(0xffffffffu, sum, 1);
            sum += __shfl_xor_sync(0xffffffffu, sum, 2);
            lrow[h] = lrow[h] * corr + sum;
#pragma unroll
            for (int na = 0; na < 8; na++) {
                of[na][h * 2 + 0] *= corr;
                of[na][h * 2 + 1] *= corr;
            }
        }

        // ---- O += P V (register P hi-only, 1-pass) ----
#pragma unroll
        for (int ka = 0; ka < 4; ka++) {
            uint32_t pah[4];
            pah[0] = pack2(sacc[2 * ka][0],     sacc[2 * ka][1]);
            pah[1] = pack2(sacc[2 * ka][2],     sacc[2 * ka][3]);
            pah[2] = pack2(sacc[2 * ka + 1][0], sacc[2 * ka + 1][1]);
            pah[3] = pack2(sacc[2 * ka + 1][2], sacc[2 * ka + 1][3]);
#pragma unroll
            for (int nb = 0; nb < 4; nb++) {
                uint32_t off = ((f_row + nb * 16) * ATS + ka * 8 + f_col) * 4;
                uint32_t vh4[4];
                ldsm4(vh4, st + A_VHI * 4 + off);
                mma16(of[2 * nb],     pah, &vh4[0]);
                mma16(of[2 * nb + 1], pah, &vh4[2]);
            }
        }
    }

    // ---- finalize: write O hi fp16 pairs ----
    const int bb = bh >> 4, hh = bh & 15;
    float inv0 = 1.f / lrow[0];
    float inv1 = 1.f / lrow[1];
    int q = qb * 128 + wrow + g;
    size_t r0 = (size_t)(bb * T_ + q) * 512 + hh * 32;
    size_t r8 = r0 + 8 * 512;
#pragma unroll
    for (int na = 0; na < 8; na++) {
        int dp = (na * 8 + tg * 2) >> 1;
        g_Oh[r0 + dp] = pack2(of[na][0] * inv0, of[na][1] * inv0);
        g_Oh[r8 + dp] = pack2(of[na][2] * inv1, of[na][3] * inv1);
    }
}

// ---------------- launch ----------------
extern "C" void kernel_launch(void* const* d_in, const int* in_sizes, int n_in,
                              void* d_out, int out_size)
{
    const float* x    = (const float*)d_in[0];
    const float* Wqkv = (const float*)d_in[1];
    const float* bqkv = (const float*)d_in[2];
    const float* Wout = (const float*)d_in[3];
    const float* bout = (const float*)d_in[4];
    float* out = (float*)d_out;

    static bool attr_done = false;
    if (!attr_done) {
        cudaFuncSetAttribute((void*)gemmb<0>, cudaFuncAttributeMaxDynamicSharedMemorySize, GEMM_SMEM);
        cudaFuncSetAttribute((void*)gemmb<1>, cudaFuncAttributeMaxDynamicSharedMemorySize, GEMM_SMEM);
        cudaFuncSetAttribute((void*)attnb,    cudaFuncAttributeMaxDynamicSharedMemorySize, ATTN_SMEM);
        attr_done = true;
    }

    prep_x<<<4096 * 512 / 256, 256>>>(x);
    prep_w<N1, 0><<<dim3(N1 / 64, 16), 256>>>(Wqkv);
    prep_w<N2, 1><<<dim3(N2 / 64, 16), 256>>>(Wout);

    dim3 g1(N1 / 128, M_ / 128);   // (24, 32)
    gemmb<0><<<g1, 256, GEMM_SMEM>>>(bqkv, nullptr);

    dim3 ga(T_ / 128, B_ * H_);    // (16, 32)
    attnb<<<ga, 256, ATTN_SMEM>>>();

    dim3 g2(N2 / 128, M_ / 128);   // (8, 32)
    gemmb<1><<<g2, 256, GEMM_SMEM>>>(bout, out);
}